// round 1
// baseline (speedup 1.0000x reference)
#include <cuda_runtime.h>
#include <math.h>

// Problem constants
#define BB 4
#define TT 2048
#define CC 1024
#define HH 8
#define DH 128
#define DFF 4096
#define MM (BB*TT)   // 8192

// Scratch (device globals: allocation-free)
__device__ float g_h[(size_t)MM * CC];                    // 32 MB  (LN outputs)
__device__ float g_qkv[(size_t)3 * HH * MM * DH];         // 96 MB  q|k|v, layout [mat][head][m][d]
__device__ float g_S[(size_t)HH * BB * TT * TT];          // 512 MB (scores / ff1 reuse)

// ---------------------------------------------------------------------------
// LayerNorm over rows of length 1024. One block (256 thr) per row.
// ---------------------------------------------------------------------------
__global__ void __launch_bounds__(256) ln1024_kernel(
    const float* __restrict__ x, const float* __restrict__ gam,
    const float* __restrict__ bet, float* __restrict__ out)
{
    __shared__ float red[256];
    const int tid = threadIdx.x;
    const size_t row = blockIdx.x;
    const float4 xv = ((const float4*)(x + row * CC))[tid];

    float s = xv.x + xv.y + xv.z + xv.w;
    red[tid] = s; __syncthreads();
    for (int st = 128; st > 0; st >>= 1) {
        if (tid < st) red[tid] += red[tid + st];
        __syncthreads();
    }
    const float mu = red[0] * (1.0f / CC);
    __syncthreads();

    float dx = xv.x - mu, dy = xv.y - mu, dz = xv.z - mu, dw = xv.w - mu;
    red[tid] = dx*dx + dy*dy + dz*dz + dw*dw; __syncthreads();
    for (int st = 128; st > 0; st >>= 1) {
        if (tid < st) red[tid] += red[tid + st];
        __syncthreads();
    }
    const float var = red[0] * (1.0f / CC);
    const float rs = rsqrtf(var + 1e-5f);

    const float4 g4 = ((const float4*)gam)[tid];
    const float4 b4 = ((const float4*)bet)[tid];
    float4 o;
    o.x = dx * rs * g4.x + b4.x;
    o.y = dy * rs * g4.y + b4.y;
    o.z = dz * rs * g4.z + b4.z;
    o.w = dw * rs * g4.w + b4.w;
    ((float4*)(out + row * CC))[tid] = o;
}

// ---------------------------------------------------------------------------
// Row softmax over 2048 columns, in place. One block (256 thr) per row.
// ---------------------------------------------------------------------------
__global__ void __launch_bounds__(256) softmax2048_kernel(float* __restrict__ S)
{
    __shared__ float red[256];
    const int tid = threadIdx.x;
    float* p = S + (size_t)blockIdx.x * TT;

    float4 v0 = ((const float4*)p)[tid * 2];
    float4 v1 = ((const float4*)p)[tid * 2 + 1];

    float lmax = fmaxf(fmaxf(fmaxf(v0.x, v0.y), fmaxf(v0.z, v0.w)),
                       fmaxf(fmaxf(v1.x, v1.y), fmaxf(v1.z, v1.w)));
    red[tid] = lmax; __syncthreads();
    for (int st = 128; st > 0; st >>= 1) {
        if (tid < st) red[tid] = fmaxf(red[tid], red[tid + st]);
        __syncthreads();
    }
    const float m = red[0];
    __syncthreads();

    v0.x = __expf(v0.x - m); v0.y = __expf(v0.y - m);
    v0.z = __expf(v0.z - m); v0.w = __expf(v0.w - m);
    v1.x = __expf(v1.x - m); v1.y = __expf(v1.y - m);
    v1.z = __expf(v1.z - m); v1.w = __expf(v1.w - m);

    red[tid] = v0.x+v0.y+v0.z+v0.w + v1.x+v1.y+v1.z+v1.w; __syncthreads();
    for (int st = 128; st > 0; st >>= 1) {
        if (tid < st) red[tid] += red[tid + st];
        __syncthreads();
    }
    const float inv = 1.0f / red[0];

    v0.x *= inv; v0.y *= inv; v0.z *= inv; v0.w *= inv;
    v1.x *= inv; v1.y *= inv; v1.z *= inv; v1.w *= inv;
    ((float4*)p)[tid * 2]     = v0;
    ((float4*)p)[tid * 2 + 1] = v1;
}

// ---------------------------------------------------------------------------
// Tiled fp32 GEMM: C = alpha * A(MxK) * B + epilogue. 64x64x16 tiles, 256 thr,
// 4x4 microtile per thread. TRANSB=true: B given as (N x K) row-major (NT).
// Batched via blockIdx.z with generic two-level offsets:
//   off(z) = (z / zdiv) * s1 + (z % zdiv) * s2
// All dims are assumed to divide the tile sizes exactly (true for this block).
// EPI: 0 = none; 1 = relu(acc + bias[n]); 2 = acc + bias[n] + res; 3 = acc + res
// ---------------------------------------------------------------------------
template<bool TRANSB, int EPI>
__global__ void __launch_bounds__(256) gemm64_kernel(
    const float* __restrict__ A, const float* __restrict__ Bm,
    float* __restrict__ C, const float* __restrict__ bias,
    const float* __restrict__ res,
    int lda, int ldb, int ldc, int K,
    int zdiv, long aS1, long aS2, long bS1, long bS2, long cS1, long cS2,
    float alpha)
{
    __shared__ float As[16][64];
    __shared__ float Bs[16][64];

    const int tid = threadIdx.x;
    const int z   = blockIdx.z;
    const int zq  = z / zdiv, zr = z % zdiv;
    const size_t aOff = (size_t)zq * aS1 + (size_t)zr * aS2;
    const size_t bOff = (size_t)zq * bS1 + (size_t)zr * bS2;
    const size_t cOff = (size_t)zq * cS1 + (size_t)zr * cS2;

    const int m0 = blockIdx.y * 64;
    const int n0 = blockIdx.x * 64;
    const int tm = tid >> 4;        // 0..15
    const int tn = tid & 15;        // 0..15

    const int ar  = tid >> 2;       // 0..63
    const int akq = (tid & 3) << 2; // 0,4,8,12
    const int bkr = tid >> 4;       // 0..15
    const int bnq = (tid & 15) << 2;

    float acc[4][4] = {};

    for (int k0 = 0; k0 < K; k0 += 16) {
        // Load A tile (64 x 16) transposed into As[k][m]
        {
            const float4 av = *(const float4*)(A + aOff + (size_t)(m0 + ar) * lda + (k0 + akq));
            As[akq + 0][ar] = av.x;
            As[akq + 1][ar] = av.y;
            As[akq + 2][ar] = av.z;
            As[akq + 3][ar] = av.w;
        }
        if (TRANSB) {
            // B is (N x K) row-major; Bs[k][n] = B[n][k]
            const float4 bv = *(const float4*)(Bm + bOff + (size_t)(n0 + ar) * ldb + (k0 + akq));
            Bs[akq + 0][ar] = bv.x;
            Bs[akq + 1][ar] = bv.y;
            Bs[akq + 2][ar] = bv.z;
            Bs[akq + 3][ar] = bv.w;
        } else {
            // B is (K x N) row-major
            *(float4*)&Bs[bkr][bnq] =
                *(const float4*)(Bm + bOff + (size_t)(k0 + bkr) * ldb + (n0 + bnq));
        }
        __syncthreads();

        #pragma unroll
        for (int kk = 0; kk < 16; kk++) {
            const float4 a = *(const float4*)&As[kk][tm << 2];
            const float4 b = *(const float4*)&Bs[kk][tn << 2];
            acc[0][0] += a.x * b.x; acc[0][1] += a.x * b.y;
            acc[0][2] += a.x * b.z; acc[0][3] += a.x * b.w;
            acc[1][0] += a.y * b.x; acc[1][1] += a.y * b.y;
            acc[1][2] += a.y * b.z; acc[1][3] += a.y * b.w;
            acc[2][0] += a.z * b.x; acc[2][1] += a.z * b.y;
            acc[2][2] += a.z * b.z; acc[2][3] += a.z * b.w;
            acc[3][0] += a.w * b.x; acc[3][1] += a.w * b.y;
            acc[3][2] += a.w * b.z; acc[3][3] += a.w * b.w;
        }
        __syncthreads();
    }

    #pragma unroll
    for (int i = 0; i < 4; i++) {
        const int m = m0 + (tm << 2) + i;
        #pragma unroll
        for (int j = 0; j < 4; j++) {
            const int n = n0 + (tn << 2) + j;
            float v = acc[i][j] * alpha;
            if (EPI == 1) { v += bias[n]; v = fmaxf(v, 0.0f); }
            else if (EPI == 2) { v += bias[n] + res[cOff + (size_t)m * ldc + n]; }
            else if (EPI == 3) { v += res[cOff + (size_t)m * ldc + n]; }
            C[cOff + (size_t)m * ldc + n] = v;
        }
    }
}

// ---------------------------------------------------------------------------
// Launcher
// ---------------------------------------------------------------------------
extern "C" void kernel_launch(void* const* d_in, const int* in_sizes, int n_in,
                              void* d_out, int out_size)
{
    const float* x     = (const float*)d_in[0];
    const float* wq    = (const float*)d_in[1];
    const float* wk    = (const float*)d_in[2];
    const float* wv    = (const float*)d_in[3];
    const float* w1    = (const float*)d_in[4];
    const float* b1    = (const float*)d_in[5];
    const float* w2    = (const float*)d_in[6];
    const float* b2    = (const float*)d_in[7];
    const float* ln1g  = (const float*)d_in[8];
    const float* ln1b  = (const float*)d_in[9];
    const float* ln2g  = (const float*)d_in[10];
    const float* ln2b  = (const float*)d_in[11];
    float* out = (float*)d_out;

    float *h, *qkv, *S;
    cudaGetSymbolAddress((void**)&h,   g_h);
    cudaGetSymbolAddress((void**)&qkv, g_qkv);
    cudaGetSymbolAddress((void**)&S,   g_S);

    const long headMat = (long)HH * MM * DH;   // stride between q|k|v blocks

    // 1) h = LN1(x)
    ln1024_kernel<<<MM, 256>>>(x, ln1g, ln1b, h);

    // 2) QKV projections: per head GEMM (8192 x 1024) x (1024 x 128)
    //    output layout [mat][head][m][d]
    const float* Ws[3] = { wq, wk, wv };
    for (int mat = 0; mat < 3; mat++) {
        gemm64_kernel<false, 0><<<dim3(DH / 64, MM / 64, HH), 256>>>(
            h, Ws[mat], qkv + (size_t)mat * headMat, nullptr, nullptr,
            CC, DH, DH, CC,
            1, 0, 0, (long)CC * DH, 0, (long)MM * DH, 0,
            1.0f);
    }

    // 3) scores: S[z] = q[z] @ k[z]^T * sqrt(Dh),  z = head*4 + b  (32 batches)
    gemm64_kernel<true, 0><<<dim3(TT / 64, TT / 64, HH * BB), 256>>>(
        qkv, qkv + headMat, S, nullptr, nullptr,
        DH, DH, TT, DH,
        1, (long)TT * DH, 0, (long)TT * DH, 0, (long)TT * TT, 0,
        sqrtf((float)DH));

    // 4) softmax over rows
    softmax2048_kernel<<<HH * BB * TT, 256>>>(S);

    // 5) O = P @ V, scattered to (B,T,C) with residual x; out = x + attn_out
    //    z = head*4 + b;  cOff = head*Dh + b*T*C
    gemm64_kernel<false, 3><<<dim3(DH / 64, TT / 64, HH * BB), 256>>>(
        S, qkv + 2 * headMat, out, nullptr, x,
        TT, DH, CC, TT,
        4, 4L * TT * TT, (long)TT * TT,
           4L * TT * DH, (long)TT * DH,
           (long)DH,     (long)TT * CC,
        1.0f);

    // 6) h = LN2(out)
    ln1024_kernel<<<MM, 256>>>(out, ln2g, ln2b, h);

    // 7) ff1 = relu(h @ w1 + b1)  -> reuse S as scratch (128 MB < 512 MB)
    gemm64_kernel<false, 1><<<dim3(DFF / 64, MM / 64, 1), 256>>>(
        h, w1, S, b1, nullptr,
        CC, DFF, DFF, CC,
        1, 0, 0, 0, 0, 0, 0,
        1.0f);

    // 8) out = out + ff1 @ w2 + b2
    gemm64_kernel<false, 2><<<dim3(CC / 64, MM / 64, 1), 256>>>(
        S, w2, out, b2, out,
        DFF, CC, CC, DFF,
        1, 0, 0, 0, 0, 0, 0,
        1.0f);
}

// round 2
// speedup vs baseline: 1.4066x; 1.4066x over previous
#include <cuda_runtime.h>
#include <math.h>

// Problem constants
#define BB 4
#define TT 2048
#define CC 1024
#define HH 8
#define DH 128
#define DFF 4096
#define MM (BB*TT)   // 8192

// Scratch (device globals: allocation-free)
__device__ float g_h[(size_t)MM * CC];                    // 32 MB  (LN outputs)
__device__ float g_qkv[(size_t)3 * HH * MM * DH];         // 96 MB  q|k|v, layout [mat][head][m][d]
__device__ float g_S[(size_t)HH * BB * TT * TT];          // 512 MB (scores / ff1 reuse)

// ---------------------------------------------------------------------------
// LayerNorm over rows of length 1024. One block (256 thr) per row.
// ---------------------------------------------------------------------------
__global__ void __launch_bounds__(256) ln1024_kernel(
    const float* __restrict__ x, const float* __restrict__ gam,
    const float* __restrict__ bet, float* __restrict__ out)
{
    __shared__ float red[256];
    const int tid = threadIdx.x;
    const size_t row = blockIdx.x;
    const float4 xv = ((const float4*)(x + row * CC))[tid];

    float s = xv.x + xv.y + xv.z + xv.w;
    red[tid] = s; __syncthreads();
    for (int st = 128; st > 0; st >>= 1) {
        if (tid < st) red[tid] += red[tid + st];
        __syncthreads();
    }
    const float mu = red[0] * (1.0f / CC);
    __syncthreads();

    float dx = xv.x - mu, dy = xv.y - mu, dz = xv.z - mu, dw = xv.w - mu;
    red[tid] = dx*dx + dy*dy + dz*dz + dw*dw; __syncthreads();
    for (int st = 128; st > 0; st >>= 1) {
        if (tid < st) red[tid] += red[tid + st];
        __syncthreads();
    }
    const float var = red[0] * (1.0f / CC);
    const float rs = rsqrtf(var + 1e-5f);

    const float4 g4 = ((const float4*)gam)[tid];
    const float4 b4 = ((const float4*)bet)[tid];
    float4 o;
    o.x = dx * rs * g4.x + b4.x;
    o.y = dy * rs * g4.y + b4.y;
    o.z = dz * rs * g4.z + b4.z;
    o.w = dw * rs * g4.w + b4.w;
    ((float4*)(out + row * CC))[tid] = o;
}

// ---------------------------------------------------------------------------
// Row softmax over 2048 columns, in place. One block (256 thr) per row.
// ---------------------------------------------------------------------------
__global__ void __launch_bounds__(256) softmax2048_kernel(float* __restrict__ S)
{
    __shared__ float red[256];
    const int tid = threadIdx.x;
    float* p = S + (size_t)blockIdx.x * TT;

    float4 v0 = ((const float4*)p)[tid * 2];
    float4 v1 = ((const float4*)p)[tid * 2 + 1];

    float lmax = fmaxf(fmaxf(fmaxf(v0.x, v0.y), fmaxf(v0.z, v0.w)),
                       fmaxf(fmaxf(v1.x, v1.y), fmaxf(v1.z, v1.w)));
    red[tid] = lmax; __syncthreads();
    for (int st = 128; st > 0; st >>= 1) {
        if (tid < st) red[tid] = fmaxf(red[tid], red[tid + st]);
        __syncthreads();
    }
    const float m = red[0];
    __syncthreads();

    v0.x = __expf(v0.x - m); v0.y = __expf(v0.y - m);
    v0.z = __expf(v0.z - m); v0.w = __expf(v0.w - m);
    v1.x = __expf(v1.x - m); v1.y = __expf(v1.y - m);
    v1.z = __expf(v1.z - m); v1.w = __expf(v1.w - m);

    red[tid] = v0.x+v0.y+v0.z+v0.w + v1.x+v1.y+v1.z+v1.w; __syncthreads();
    for (int st = 128; st > 0; st >>= 1) {
        if (tid < st) red[tid] += red[tid + st];
        __syncthreads();
    }
    const float inv = 1.0f / red[0];

    v0.x *= inv; v0.y *= inv; v0.z *= inv; v0.w *= inv;
    v1.x *= inv; v1.y *= inv; v1.z *= inv; v1.w *= inv;
    ((float4*)p)[tid * 2]     = v0;
    ((float4*)p)[tid * 2 + 1] = v1;
}

// ---------------------------------------------------------------------------
// Tiled fp32 GEMM: C = alpha * A(MxK) * B + epilogue.
// 128x128 block tile, Ktile=8, 256 threads, 8x8 microtile (split 4+4 halves),
// double-buffered shared memory with gmem->reg->smem pipelining.
// TRANSB=true: B given as (N x K) row-major (NT).
// Batched via blockIdx.z: off(z) = (z / zdiv) * s1 + (z % zdiv) * s2
// All dims divide tile sizes exactly (true for every call in this block).
// EPI: 0 = none; 1 = relu(acc + bias[n]); 2 = acc + bias[n] + res; 3 = acc + res
// ---------------------------------------------------------------------------
template<bool TRANSB, int EPI>
__global__ void __launch_bounds__(256, 2) gemm128_kernel(
    const float* __restrict__ A, const float* __restrict__ Bm,
    float* __restrict__ C, const float* __restrict__ bias,
    const float* __restrict__ res,
    int lda, int ldb, int ldc, int K,
    int zdiv, long aS1, long aS2, long bS1, long bS2, long cS1, long cS2,
    float alpha)
{
    __shared__ float As[2][8][128];
    __shared__ float Bs[2][8][128];

    const int tid = threadIdx.x;
    const int z   = blockIdx.z;
    const int zq  = z / zdiv, zr = z % zdiv;
    const size_t aOff = (size_t)zq * aS1 + (size_t)zr * aS2;
    const size_t bOff = (size_t)zq * bS1 + (size_t)zr * bS2;
    const size_t cOff = (size_t)zq * cS1 + (size_t)zr * cS2;

    const int m0 = blockIdx.y * 128;
    const int n0 = blockIdx.x * 128;
    const int tm = (tid >> 4) << 2;   // 0,4,..,60
    const int tn = (tid & 15) << 2;   // 0,4,..,60

    // A (and trans-B) loader mapping: one float4 per thread per tile
    const int ar  = tid >> 1;         // 0..127 (row within tile)
    const int akq = (tid & 1) << 2;   // 0 or 4 (k within tile)
    // non-trans B loader mapping
    const int bkr = tid >> 5;         // 0..7
    const int bnq = (tid & 31) << 2;  // 0..124

    const float* Aload = A + aOff + (size_t)(m0 + ar) * lda + akq;
    const float* Bload = TRANSB
        ? (Bm + bOff + (size_t)(n0 + ar) * ldb + akq)
        : (Bm + bOff + (size_t)bkr * ldb + (n0 + bnq));

    float acc[8][8] = {};
    float4 aReg, bReg;

    // prologue: load tile 0 into buffer 0
    aReg = *(const float4*)(Aload);
    bReg = *(const float4*)(Bload);
    As[0][akq + 0][ar] = aReg.x;
    As[0][akq + 1][ar] = aReg.y;
    As[0][akq + 2][ar] = aReg.z;
    As[0][akq + 3][ar] = aReg.w;
    if (TRANSB) {
        Bs[0][akq + 0][ar] = bReg.x;
        Bs[0][akq + 1][ar] = bReg.y;
        Bs[0][akq + 2][ar] = bReg.z;
        Bs[0][akq + 3][ar] = bReg.w;
    } else {
        *(float4*)&Bs[0][bkr][bnq] = bReg;
    }
    __syncthreads();

    const int nIter = K >> 3;
    for (int kt = 0; kt < nIter; kt++) {
        const int buf = kt & 1;
        // issue global loads for next tile early (hide latency under compute)
        if (kt + 1 < nIter) {
            const int kn = (kt + 1) << 3;
            aReg = *(const float4*)(Aload + kn);
            bReg = TRANSB ? *(const float4*)(Bload + kn)
                          : *(const float4*)(Bload + (size_t)kn * ldb);
        }

        #pragma unroll
        for (int kk = 0; kk < 8; kk++) {
            const float4 a0 = *(const float4*)&As[buf][kk][tm];
            const float4 a1 = *(const float4*)&As[buf][kk][tm + 64];
            const float4 b0 = *(const float4*)&Bs[buf][kk][tn];
            const float4 b1 = *(const float4*)&Bs[buf][kk][tn + 64];
            const float av[8] = {a0.x,a0.y,a0.z,a0.w,a1.x,a1.y,a1.z,a1.w};
            const float bv[8] = {b0.x,b0.y,b0.z,b0.w,b1.x,b1.y,b1.z,b1.w};
            #pragma unroll
            for (int i = 0; i < 8; i++)
                #pragma unroll
                for (int j = 0; j < 8; j++)
                    acc[i][j] += av[i] * bv[j];
        }

        if (kt + 1 < nIter) {
            const int nbuf = buf ^ 1;
            As[nbuf][akq + 0][ar] = aReg.x;
            As[nbuf][akq + 1][ar] = aReg.y;
            As[nbuf][akq + 2][ar] = aReg.z;
            As[nbuf][akq + 3][ar] = aReg.w;
            if (TRANSB) {
                Bs[nbuf][akq + 0][ar] = bReg.x;
                Bs[nbuf][akq + 1][ar] = bReg.y;
                Bs[nbuf][akq + 2][ar] = bReg.z;
                Bs[nbuf][akq + 3][ar] = bReg.w;
            } else {
                *(float4*)&Bs[nbuf][bkr][bnq] = bReg;
            }
            __syncthreads();
        }
    }

    // epilogue: 8x8 result at rows {m0+tm+i, m0+64+tm+i}, cols {n0+tn+j, n0+64+tn+j}
    #pragma unroll
    for (int i = 0; i < 8; i++) {
        const int m = m0 + ((i < 4) ? (tm + i) : (64 + tm + i - 4));
        #pragma unroll
        for (int j = 0; j < 8; j++) {
            const int n = n0 + ((j < 4) ? (tn + j) : (64 + tn + j - 4));
            float v = acc[i][j] * alpha;
            if (EPI == 1) { v += bias[n]; v = fmaxf(v, 0.0f); }
            else if (EPI == 2) { v += bias[n] + res[cOff + (size_t)m * ldc + n]; }
            else if (EPI == 3) { v += res[cOff + (size_t)m * ldc + n]; }
            C[cOff + (size_t)m * ldc + n] = v;
        }
    }
}

// ---------------------------------------------------------------------------
// Launcher
// ---------------------------------------------------------------------------
extern "C" void kernel_launch(void* const* d_in, const int* in_sizes, int n_in,
                              void* d_out, int out_size)
{
    const float* x     = (const float*)d_in[0];
    const float* wq    = (const float*)d_in[1];
    const float* wk    = (const float*)d_in[2];
    const float* wv    = (const float*)d_in[3];
    const float* w1    = (const float*)d_in[4];
    const float* b1    = (const float*)d_in[5];
    const float* w2    = (const float*)d_in[6];
    const float* b2    = (const float*)d_in[7];
    const float* ln1g  = (const float*)d_in[8];
    const float* ln1b  = (const float*)d_in[9];
    const float* ln2g  = (const float*)d_in[10];
    const float* ln2b  = (const float*)d_in[11];
    float* out = (float*)d_out;

    float *h, *qkv, *S;
    cudaGetSymbolAddress((void**)&h,   g_h);
    cudaGetSymbolAddress((void**)&qkv, g_qkv);
    cudaGetSymbolAddress((void**)&S,   g_S);

    const long headMat = (long)HH * MM * DH;   // stride between q|k|v blocks

    // 1) h = LN1(x)
    ln1024_kernel<<<MM, 256>>>(x, ln1g, ln1b, h);

    // 2) QKV projections: per head GEMM (8192 x 1024) x (1024 x 128)
    //    output layout [mat][head][m][d]
    const float* Ws[3] = { wq, wk, wv };
    for (int mat = 0; mat < 3; mat++) {
        gemm128_kernel<false, 0><<<dim3(DH / 128, MM / 128, HH), 256>>>(
            h, Ws[mat], qkv + (size_t)mat * headMat, nullptr, nullptr,
            CC, DH, DH, CC,
            1, 0, 0, (long)CC * DH, 0, (long)MM * DH, 0,
            1.0f);
    }

    // 3) scores: S[z] = q[z] @ k[z]^T * sqrt(Dh),  z = head*4 + b  (32 batches)
    gemm128_kernel<true, 0><<<dim3(TT / 128, TT / 128, HH * BB), 256>>>(
        qkv, qkv + headMat, S, nullptr, nullptr,
        DH, DH, TT, DH,
        1, (long)TT * DH, 0, (long)TT * DH, 0, (long)TT * TT, 0,
        sqrtf((float)DH));

    // 4) softmax over rows
    softmax2048_kernel<<<HH * BB * TT, 256>>>(S);

    // 5) O = P @ V, scattered to (B,T,C) with residual x; out = x + attn_out
    //    z = head*4 + b;  cOff = head*Dh + b*T*C
    gemm128_kernel<false, 3><<<dim3(DH / 128, TT / 128, HH * BB), 256>>>(
        S, qkv + 2 * headMat, out, nullptr, x,
        TT, DH, CC, TT,
        4, 4L * TT * TT, (long)TT * TT,
           4L * TT * DH, (long)TT * DH,
           (long)DH,     (long)TT * CC,
        1.0f);

    // 6) h = LN2(out)
    ln1024_kernel<<<MM, 256>>>(out, ln2g, ln2b, h);

    // 7) ff1 = relu(h @ w1 + b1)  -> reuse S as scratch (128 MB < 512 MB)
    gemm128_kernel<false, 1><<<dim3(DFF / 128, MM / 128, 1), 256>>>(
        h, w1, S, b1, nullptr,
        CC, DFF, DFF, CC,
        1, 0, 0, 0, 0, 0, 0,
        1.0f);

    // 8) out = out + ff1 @ w2 + b2
    gemm128_kernel<false, 2><<<dim3(CC / 128, MM / 128, 1), 256>>>(
        S, w2, out, b2, out,
        DFF, CC, CC, DFF,
        1, 0, 0, 0, 0, 0, 0,
        1.0f);
}

// round 5
// speedup vs baseline: 2.5870x; 1.8392x over previous
#include <cuda_runtime.h>
#include <cuda_bf16.h>
#include <math.h>
#include <stdint.h>

typedef __nv_bfloat16 bf16;

#define BB 4
#define TT 2048
#define CC 1024
#define HH 8
#define DH 128
#define DFF 4096
#define MM (BB*TT)   // 8192

#define HEADMAT ((size_t)HH * MM * DH)          // 8,388,608
#define WOFFW1  ((size_t)3 * HH * DH * CC)
#define WOFFW2  (WOFFW1 + (size_t)DFF * CC)
#define WTOTAL  (WOFFW2 + (size_t)CC * DFF)

// ------------------------- device scratch (allocation-free) -----------------
__device__ bf16 g_hhi[(size_t)MM * CC];
__device__ bf16 g_hlo[(size_t)MM * CC];
__device__ bf16 g_qhi[(size_t)3 * HEADMAT];      // q | k | v
__device__ bf16 g_qlo[(size_t)3 * HEADMAT];
__device__ bf16 g_vThi[(size_t)HH * BB * DH * TT];
__device__ bf16 g_vTlo[(size_t)HH * BB * DH * TT];
__device__ bf16 g_wThi[WTOTAL];
__device__ bf16 g_wTlo[WTOTAL];
__device__ float g_S[(size_t)HH * BB * TT * TT];          // 512 MB, reused for ff hi/lo
__device__ bf16 g_Phi[(size_t)HH * BB * TT * TT];
__device__ bf16 g_Plo[(size_t)HH * BB * TT * TT];

// ------------------------- helpers ------------------------------------------
__device__ __forceinline__ uint32_t smem_u32(const void* p) {
    uint32_t a;
    asm("{ .reg .u64 t; cvta.to.shared.u64 t, %1; cvt.u32.u64 %0, t; }" : "=r"(a) : "l"(p));
    return a;
}
__device__ __forceinline__ void cpasync16(uint32_t s, const void* g) {
    asm volatile("cp.async.cg.shared.global [%0], [%1], 16;" :: "r"(s), "l"(g));
}
#define CP_COMMIT() asm volatile("cp.async.commit_group;" ::: "memory")

#define LDSM_X4(r0, r1, r2, r3, addr) \
    asm volatile("ldmatrix.sync.aligned.m8n8.x4.shared.b16 {%0,%1,%2,%3}, [%4];" \
                 : "=r"(r0), "=r"(r1), "=r"(r2), "=r"(r3) : "r"(addr))

#define MMA16816(c, a, b) \
    asm volatile("mma.sync.aligned.m16n8k16.row.col.f32.bf16.bf16.f32 " \
                 "{%0,%1,%2,%3}, {%4,%5,%6,%7}, {%8,%9}, {%0,%1,%2,%3};" \
                 : "+f"((c)[0]), "+f"((c)[1]), "+f"((c)[2]), "+f"((c)[3]) \
                 : "r"((a)[0]), "r"((a)[1]), "r"((a)[2]), "r"((a)[3]), \
                   "r"((b)[0]), "r"((b)[1]))

__device__ __forceinline__ void split_bf16(float v, bf16& h, bf16& l) {
    h = __float2bfloat16(v);
    l = __float2bfloat16(v - __bfloat162float(h));
}

// ------------------------- LayerNorm -> bf16 hi/lo ---------------------------
__global__ void __launch_bounds__(256) ln1024_kernel(
    const float* __restrict__ x, const float* __restrict__ gam,
    const float* __restrict__ bet, bf16* __restrict__ ohi, bf16* __restrict__ olo)
{
    __shared__ float red[256];
    const int tid = threadIdx.x;
    const size_t row = blockIdx.x;
    const float4 xv = ((const float4*)(x + row * CC))[tid];

    red[tid] = xv.x + xv.y + xv.z + xv.w; __syncthreads();
    for (int st = 128; st > 0; st >>= 1) {
        if (tid < st) red[tid] += red[tid + st];
        __syncthreads();
    }
    const float mu = red[0] * (1.0f / CC);
    __syncthreads();

    float dx = xv.x - mu, dy = xv.y - mu, dz = xv.z - mu, dw = xv.w - mu;
    red[tid] = dx*dx + dy*dy + dz*dz + dw*dw; __syncthreads();
    for (int st = 128; st > 0; st >>= 1) {
        if (tid < st) red[tid] += red[tid + st];
        __syncthreads();
    }
    const float rs = rsqrtf(red[0] * (1.0f / CC) + 1e-5f);

    const float4 g4 = ((const float4*)gam)[tid];
    const float4 b4 = ((const float4*)bet)[tid];
    float o[4];
    o[0] = dx * rs * g4.x + b4.x;
    o[1] = dy * rs * g4.y + b4.y;
    o[2] = dz * rs * g4.z + b4.z;
    o[3] = dw * rs * g4.w + b4.w;

    bf16 hh[4], ll[4];
    #pragma unroll
    for (int i = 0; i < 4; i++) split_bf16(o[i], hh[i], ll[i]);
    *(uint2*)(ohi + row * CC + tid * 4) = *(const uint2*)hh;
    *(uint2*)(olo + row * CC + tid * 4) = *(const uint2*)ll;
}

// ------------------------- softmax -> bf16 hi/lo P ---------------------------
__global__ void __launch_bounds__(256) softmax2048_kernel(
    const float* __restrict__ S, bf16* __restrict__ Phi, bf16* __restrict__ Plo)
{
    __shared__ float red[256];
    const int tid = threadIdx.x;
    const float* p = S + (size_t)blockIdx.x * TT;

    float4 v0 = ((const float4*)p)[tid * 2];
    float4 v1 = ((const float4*)p)[tid * 2 + 1];

    float lmax = fmaxf(fmaxf(fmaxf(v0.x, v0.y), fmaxf(v0.z, v0.w)),
                       fmaxf(fmaxf(v1.x, v1.y), fmaxf(v1.z, v1.w)));
    red[tid] = lmax; __syncthreads();
    for (int st = 128; st > 0; st >>= 1) {
        if (tid < st) red[tid] = fmaxf(red[tid], red[tid + st]);
        __syncthreads();
    }
    const float m = red[0];
    __syncthreads();

    float e[8];
    e[0] = __expf(v0.x - m); e[1] = __expf(v0.y - m);
    e[2] = __expf(v0.z - m); e[3] = __expf(v0.w - m);
    e[4] = __expf(v1.x - m); e[5] = __expf(v1.y - m);
    e[6] = __expf(v1.z - m); e[7] = __expf(v1.w - m);

    red[tid] = e[0]+e[1]+e[2]+e[3]+e[4]+e[5]+e[6]+e[7]; __syncthreads();
    for (int st = 128; st > 0; st >>= 1) {
        if (tid < st) red[tid] += red[tid + st];
        __syncthreads();
    }
    const float inv = 1.0f / red[0];

    bf16 hh[8], ll[8];
    #pragma unroll
    for (int i = 0; i < 8; i++) split_bf16(e[i] * inv, hh[i], ll[i]);
    *(uint4*)(Phi + (size_t)blockIdx.x * TT + tid * 8) = *(const uint4*)hh;
    *(uint4*)(Plo + (size_t)blockIdx.x * TT + tid * 8) = *(const uint4*)ll;
}

// ----------------- transpose fp32 (rows x cols) -> bf16 hi/lo (cols x rows) --
__global__ void __launch_bounds__(256) transw_kernel(
    const float* __restrict__ W, bf16* __restrict__ Thi, bf16* __restrict__ Tlo,
    int rows, int cols, long inStride, long outStride)
{
    __shared__ float tile[32][33];
    const float* Win = W + (size_t)blockIdx.z * inStride;
    bf16* thi = Thi + (size_t)blockIdx.z * outStride;
    bf16* tlo = Tlo + (size_t)blockIdx.z * outStride;
    const int c0 = blockIdx.x * 32, r0 = blockIdx.y * 32;
    const int tx = threadIdx.x & 31, ty = threadIdx.x >> 5;
    #pragma unroll
    for (int i = 0; i < 4; i++) {
        int r = ty + i * 8;
        tile[r][tx] = Win[(size_t)(r0 + r) * cols + c0 + tx];
    }
    __syncthreads();
    #pragma unroll
    for (int i = 0; i < 4; i++) {
        int c = ty + i * 8;
        float v = tile[tx][c];
        bf16 h, l; split_bf16(v, h, l);
        size_t o = (size_t)(c0 + c) * rows + r0 + tx;
        thi[o] = h; tlo[o] = l;
    }
}

// ----------------- transpose V (bf16 hi/lo) -> vT [z][d][t] ------------------
__global__ void __launch_bounds__(256) transv_kernel(
    const bf16* __restrict__ Vhi, const bf16* __restrict__ Vlo,
    bf16* __restrict__ Thi, bf16* __restrict__ Tlo)
{
    __shared__ bf16 tile[2][32][33];
    const int z = blockIdx.z, h = z >> 2, b = z & 3;
    const size_t inOff  = (size_t)h * MM * DH + (size_t)b * TT * DH;
    const size_t outOff = (size_t)z * DH * TT;
    const int d0 = blockIdx.x * 32, t0 = blockIdx.y * 32;
    const int tx = threadIdx.x & 31, ty = threadIdx.x >> 5;
    #pragma unroll
    for (int i = 0; i < 4; i++) {
        int t = ty + i * 8;
        tile[0][t][tx] = Vhi[inOff + (size_t)(t0 + t) * DH + d0 + tx];
        tile[1][t][tx] = Vlo[inOff + (size_t)(t0 + t) * DH + d0 + tx];
    }
    __syncthreads();
    #pragma unroll
    for (int i = 0; i < 4; i++) {
        int d = ty + i * 8;
        size_t o = outOff + (size_t)(d0 + d) * TT + t0 + tx;
        Thi[o] = tile[0][tx][d];
        Tlo[o] = tile[1][tx][d];
    }
}

// ---------------------------------------------------------------------------
// bf16x3 split GEMM on mma.sync (m16n8k16): D(f32) = alpha * A * B^T + epilogue
//   A: M x K row-major hi/lo, B: N x K row-major hi/lo (both K-contiguous).
//   128x128 block tile, BK=32, 256 thr (8 warps: 2M x 4N, 64x32 warp tile),
//   cp.async double-buffered smem; 3 products: hi*hi + hi*lo + lo*hi.
// EPI: 0 = fp32*alpha; 1 = fp32+res; 2 = bf16 hi/lo;
//      3 = bf16 hi/lo of relu(v+bias); 4 = fp32+bias+res
// ---------------------------------------------------------------------------
#define TILE_B   10240            // 128 rows * 80 bytes
#define STAGE_B  (4 * TILE_B)     // Ahi, Alo, Bhi, Blo
#define SMEM_DYN (2 * STAGE_B)    // 81920

template<int EPI>
__global__ void __launch_bounds__(256, 1) tcgemm_kernel(
    const bf16* __restrict__ Ahi, const bf16* __restrict__ Alo,
    const bf16* __restrict__ Bhi, const bf16* __restrict__ Blo,
    float* __restrict__ Cf, bf16* __restrict__ Chi, bf16* __restrict__ Clo,
    const float* __restrict__ bias, const float* __restrict__ res,
    int lda, int ldb, int ldc, int K,
    int zdiv, long aS1, long aS2, long bS1, long bS2, long cS1, long cS2,
    float alpha)
{
    extern __shared__ char smem[];
    const uint32_t sbase = smem_u32(smem);

    const int tid  = threadIdx.x;
    const int lane = tid & 31;
    const int wid  = tid >> 5;
    const int wm   = wid >> 2;      // 0..1
    const int wn   = wid & 3;       // 0..3

    const int z  = blockIdx.z;
    const int zq = z / zdiv, zr = z % zdiv;
    const size_t aOff = (size_t)zq * aS1 + (size_t)zr * aS2;
    const size_t bOff = (size_t)zq * bS1 + (size_t)zr * bS2;
    const size_t cOff = (size_t)zq * cS1 + (size_t)zr * cS2;
    const int m0 = blockIdx.y * 128;
    const int n0 = blockIdx.x * 128;

    // ---- loader mapping: tile = tid>>6 (Ahi,Alo,Bhi,Blo), 64 thr/tile ----
    const int tile = tid >> 6;
    const int u    = tid & 63;
    const int lrow = u >> 2;                 // 0..15 (rows lrow + 16*j)
    const int lchk = (u & 3) * 8;            // element offset within 32-K chunk
    const bf16* gp;
    int ld;
    if      (tile == 0) { gp = Ahi + aOff + (size_t)(m0 + lrow) * lda; ld = lda; }
    else if (tile == 1) { gp = Alo + aOff + (size_t)(m0 + lrow) * lda; ld = lda; }
    else if (tile == 2) { gp = Bhi + bOff + (size_t)(n0 + lrow) * ldb; ld = ldb; }
    else                { gp = Blo + bOff + (size_t)(n0 + lrow) * ldb; ld = ldb; }
    gp += lchk;
    const uint32_t sdst0 = sbase + tile * TILE_B + lrow * 80 + lchk * 2;

    const int nst = K >> 5;       // K / 32

    // prologue: stage 0 -> buf 0
    {
        const bf16* g = gp;
        #pragma unroll
        for (int j = 0; j < 8; j++)
            cpasync16(sdst0 + j * 16 * 80, g + (size_t)j * 16 * ld);
        CP_COMMIT();
    }

    float acc[4][4][4] = {};

    for (int kt = 0; kt < nst; kt++) {
        const int buf = kt & 1;
        if (kt + 1 < nst) {
            const bf16* g = gp + (kt + 1) * 32;
            const uint32_t sd = sdst0 + ((kt + 1) & 1) * STAGE_B;
            #pragma unroll
            for (int j = 0; j < 8; j++)
                cpasync16(sd + j * 16 * 80, g + (size_t)j * 16 * ld);
            CP_COMMIT();
            asm volatile("cp.async.wait_group 1;" ::: "memory");
        } else {
            asm volatile("cp.async.wait_group 0;" ::: "memory");
        }
        __syncthreads();

        const uint32_t sb   = sbase + buf * STAGE_B;
        const uint32_t sAhi = sb;
        const uint32_t sAlo = sb + TILE_B;
        const uint32_t sBhi = sb + 2 * TILE_B;
        const uint32_t sBlo = sb + 3 * TILE_B;

        #pragma unroll
        for (int ks = 0; ks < 2; ks++) {
            const int k16 = ks * 16;
            uint32_t ahi[4][4], alo[4][4], bhi[4][2], blo[4][2];

            const uint32_t aoffl = (k16 + ((lane >> 4) << 3)) * 2;
            #pragma unroll
            for (int i = 0; i < 4; i++) {
                const uint32_t ro = (uint32_t)(wm * 64 + i * 16 + (lane & 15)) * 80 + aoffl;
                LDSM_X4(ahi[i][0], ahi[i][1], ahi[i][2], ahi[i][3], sAhi + ro);
                LDSM_X4(alo[i][0], alo[i][1], alo[i][2], alo[i][3], sAlo + ro);
            }
            const uint32_t boffl = (k16 + (lane & 8)) * 2;
            #pragma unroll
            for (int p = 0; p < 2; p++) {
                const uint32_t ro =
                    (uint32_t)(wn * 32 + p * 16 + ((lane >> 4) << 3) + (lane & 7)) * 80 + boffl;
                LDSM_X4(bhi[p*2][0], bhi[p*2][1], bhi[p*2+1][0], bhi[p*2+1][1], sBhi + ro);
                LDSM_X4(blo[p*2][0], blo[p*2][1], blo[p*2+1][0], blo[p*2+1][1], sBlo + ro);
            }

            #pragma unroll
            for (int mi = 0; mi < 4; mi++)
                #pragma unroll
                for (int ni = 0; ni < 4; ni++) {
                    MMA16816(acc[mi][ni], ahi[mi], bhi[ni]);
                    MMA16816(acc[mi][ni], ahi[mi], blo[ni]);
                    MMA16816(acc[mi][ni], alo[mi], bhi[ni]);
                }
        }
        __syncthreads();
    }

    // ---- epilogue ----
    const int gr  = lane >> 2;
    const int gc2 = (lane & 3) * 2;
    #pragma unroll
    for (int mi = 0; mi < 4; mi++) {
        #pragma unroll
        for (int hh2 = 0; hh2 < 2; hh2++) {
            const int m = m0 + wm * 64 + mi * 16 + hh2 * 8 + gr;
            const size_t rowix = cOff + (size_t)m * ldc + n0 + wn * 32;
            #pragma unroll
            for (int ni = 0; ni < 4; ni++) {
                const int nn = ni * 8 + gc2;
                const int ncol = n0 + wn * 32 + nn;
                float v0 = acc[mi][ni][hh2 * 2 + 0];
                float v1 = acc[mi][ni][hh2 * 2 + 1];
                if (EPI == 0) {
                    float2 o = make_float2(v0 * alpha, v1 * alpha);
                    *(float2*)(Cf + rowix + nn) = o;
                } else if (EPI == 1) {
                    float2 r = *(const float2*)(res + rowix + nn);
                    *(float2*)(Cf + rowix + nn) = make_float2(v0 + r.x, v1 + r.y);
                } else if (EPI == 4) {
                    float2 r = *(const float2*)(res + rowix + nn);
                    float2 bb = *(const float2*)(bias + ncol);
                    *(float2*)(Cf + rowix + nn) = make_float2(v0 + bb.x + r.x, v1 + bb.y + r.y);
                } else {
                    if (EPI == 3) {
                        float2 bb = *(const float2*)(bias + ncol);
                        v0 = fmaxf(v0 + bb.x, 0.0f);
                        v1 = fmaxf(v1 + bb.y, 0.0f);
                    }
                    bf16 h0, l0, h1, l1;
                    split_bf16(v0, h0, l0);
                    split_bf16(v1, h1, l1);
                    bf16 hp[2] = {h0, h1}, lp[2] = {l0, l1};
                    *(uint32_t*)(Chi + rowix + nn) = *(const uint32_t*)hp;
                    *(uint32_t*)(Clo + rowix + nn) = *(const uint32_t*)lp;
                }
            }
        }
    }
}

// ---------------------------------------------------------------------------
// Launcher
// ---------------------------------------------------------------------------
extern "C" void kernel_launch(void* const* d_in, const int* in_sizes, int n_in,
                              void* d_out, int out_size)
{
    const float* x    = (const float*)d_in[0];
    const float* wq   = (const float*)d_in[1];
    const float* wk   = (const float*)d_in[2];
    const float* wv   = (const float*)d_in[3];
    const float* w1   = (const float*)d_in[4];
    const float* b1   = (const float*)d_in[5];
    const float* w2   = (const float*)d_in[6];
    const float* b2   = (const float*)d_in[7];
    const float* ln1g = (const float*)d_in[8];
    const float* ln1b = (const float*)d_in[9];
    const float* ln2g = (const float*)d_in[10];
    const float* ln2b = (const float*)d_in[11];
    float* out = (float*)d_out;

    bf16 *hhi, *hlo, *qhi, *qlo, *vThi, *vTlo, *wThi, *wTlo, *Phi, *Plo;
    float* S;
    cudaGetSymbolAddress((void**)&hhi,  g_hhi);
    cudaGetSymbolAddress((void**)&hlo,  g_hlo);
    cudaGetSymbolAddress((void**)&qhi,  g_qhi);
    cudaGetSymbolAddress((void**)&qlo,  g_qlo);
    cudaGetSymbolAddress((void**)&vThi, g_vThi);
    cudaGetSymbolAddress((void**)&vTlo, g_vTlo);
    cudaGetSymbolAddress((void**)&wThi, g_wThi);
    cudaGetSymbolAddress((void**)&wTlo, g_wTlo);
    cudaGetSymbolAddress((void**)&Phi,  g_Phi);
    cudaGetSymbolAddress((void**)&Plo,  g_Plo);
    cudaGetSymbolAddress((void**)&S,    g_S);
    bf16* ffhi = (bf16*)S;
    bf16* fflo = (bf16*)S + (size_t)MM * DFF;

    cudaFuncSetAttribute(tcgemm_kernel<0>, cudaFuncAttributeMaxDynamicSharedMemorySize, SMEM_DYN);
    cudaFuncSetAttribute(tcgemm_kernel<1>, cudaFuncAttributeMaxDynamicSharedMemorySize, SMEM_DYN);
    cudaFuncSetAttribute(tcgemm_kernel<2>, cudaFuncAttributeMaxDynamicSharedMemorySize, SMEM_DYN);
    cudaFuncSetAttribute(tcgemm_kernel<3>, cudaFuncAttributeMaxDynamicSharedMemorySize, SMEM_DYN);
    cudaFuncSetAttribute(tcgemm_kernel<4>, cudaFuncAttributeMaxDynamicSharedMemorySize, SMEM_DYN);

    // 1) h = LN1(x) -> bf16 hi/lo
    ln1024_kernel<<<MM, 256>>>(x, ln1g, ln1b, hhi, hlo);

    // 2) transpose+split weights
    transw_kernel<<<dim3(DH/32, CC/32, HH), 256>>>(wq, wThi + 0*HH*(size_t)DH*CC, wTlo + 0*HH*(size_t)DH*CC,
                                                   CC, DH, (long)CC*DH, (long)DH*CC);
    transw_kernel<<<dim3(DH/32, CC/32, HH), 256>>>(wk, wThi + 1*HH*(size_t)DH*CC, wTlo + 1*HH*(size_t)DH*CC,
                                                   CC, DH, (long)CC*DH, (long)DH*CC);
    transw_kernel<<<dim3(DH/32, CC/32, HH), 256>>>(wv, wThi + 2*HH*(size_t)DH*CC, wTlo + 2*HH*(size_t)DH*CC,
                                                   CC, DH, (long)CC*DH, (long)DH*CC);
    transw_kernel<<<dim3(DFF/32, CC/32, 1), 256>>>(w1, wThi + WOFFW1, wTlo + WOFFW1, CC, DFF, 0, 0);
    transw_kernel<<<dim3(CC/32, DFF/32, 1), 256>>>(w2, wThi + WOFFW2, wTlo + WOFFW2, DFF, CC, 0, 0);

    // 3) QKV: z = mat*8+h. A = h (M=8192, K=1024), B = wT[z] (N=128)
    tcgemm_kernel<2><<<dim3(1, MM/128, 3*HH), 256, SMEM_DYN>>>(
        hhi, hlo, wThi, wTlo,
        nullptr, qhi, qlo, nullptr, nullptr,
        CC, CC, DH, CC,
        1, 0, 0, (long)DH*CC, 0, (long)MM*DH, 0, 1.0f);

    // 4) vT transpose (per z = h*4+b)
    transv_kernel<<<dim3(DH/32, TT/32, HH*BB), 256>>>(
        qhi + 2*HEADMAT, qlo + 2*HEADMAT, vThi, vTlo);

    // 5) scores: z = h*4+b. A = q, B = k, out fp32 * sqrt(Dh)
    tcgemm_kernel<0><<<dim3(TT/128, TT/128, HH*BB), 256, SMEM_DYN>>>(
        qhi, qlo, qhi + HEADMAT, qlo + HEADMAT,
        S, nullptr, nullptr, nullptr, nullptr,
        DH, DH, TT, DH,
        BB, (long)MM*DH, (long)TT*DH, (long)MM*DH, (long)TT*DH,
            (long)BB*TT*TT, (long)TT*TT,
        sqrtf((float)DH));

    // 6) softmax -> P hi/lo
    softmax2048_kernel<<<HH*BB*TT, 256>>>(S, Phi, Plo);

    // 7) O = P @ V^T, + residual x -> out (scatter head cols)
    tcgemm_kernel<1><<<dim3(1, TT/128, HH*BB), 256, SMEM_DYN>>>(
        Phi, Plo, vThi, vTlo,
        out, nullptr, nullptr, nullptr, x,
        TT, TT, CC, TT,
        BB, (long)BB*TT*TT, (long)TT*TT, (long)BB*DH*TT, (long)DH*TT,
            (long)DH, (long)TT*CC,
        1.0f);

    // 8) h2 = LN2(out)
    ln1024_kernel<<<MM, 256>>>(out, ln2g, ln2b, hhi, hlo);

    // 9) ff = relu(h2 @ w1 + b1) -> bf16 hi/lo (into S scratch)
    tcgemm_kernel<3><<<dim3(DFF/128, MM/128, 1), 256, SMEM_DYN>>>(
        hhi, hlo, wThi + WOFFW1, wTlo + WOFFW1,
        nullptr, ffhi, fflo, b1, nullptr,
        CC, CC, DFF, CC,
        1, 0, 0, 0, 0, 0, 0, 1.0f);

    // 10) out = out + ff @ w2 + b2
    tcgemm_kernel<4><<<dim3(CC/128, MM/128, 1), 256, SMEM_DYN>>>(
        ffhi, fflo, wThi + WOFFW2, wTlo + WOFFW2,
        out, nullptr, nullptr, b2, out,
        DFF, DFF, CC, DFF,
        1, 0, 0, 0, 0, 0, 0, 1.0f);
}